// round 6
// baseline (speedup 1.0000x reference)
#include <cuda_runtime.h>
#include <cuda_bf16.h>

// Problem: B=4, L=2048, H=8, D=64.
// Reference math collapses: out[b,q,h,d] = (sum_w softmax(...)[b,q,w,h]) * (sum_e V[b,e,h,d])
//                                        = 1 * sum_l V[b,l,h,d]
// Q and K are dead inputs. Compute column-sum of V over L, broadcast over q.
// All three stages fully vectorized (LDG.128 / STG.128).

#define B_DIM 4
#define L_DIM 2048
#define HD4 128           // H*D/4 = 128 float4 per (b, l) row
#define CHUNKS 64         // L split into 64 chunks of 32 rows per batch
#define ROWS_PER_CHUNK 32

// Scratch (allocation-free: __device__ globals)
__device__ float4 g_partial4[B_DIM * CHUNKS * HD4];   // 512 KB (L2-resident)
__device__ float4 g_vsum4[B_DIM * HD4];               // 8 KB

__device__ __forceinline__ float4 f4add(float4 a, float4 b) {
    a.x += b.x; a.y += b.y; a.z += b.z; a.w += b.w; return a;
}

// Stage 1: each block sums a 32-row chunk of V into 128 float4 partials.
// Thread t: parity p = t>>7, column c = t&127. 16 independent LDG.128 per
// thread (rows p, p+2, ..., p+30), then smem-fold the two parities.
__global__ void __launch_bounds__(256) vpartial_kernel(const float4* __restrict__ V4) {
    __shared__ float4 sdata[256];
    const int b = blockIdx.y;
    const int chunk = blockIdx.x;
    const int t = threadIdx.x;
    const int p = t >> 7;          // 0 or 1
    const int c = t & 127;         // float4 column

    const float4* base = V4 + ((size_t)(b * L_DIM + chunk * ROWS_PER_CHUNK + p)) * HD4 + c;
    float4 acc = make_float4(0.f, 0.f, 0.f, 0.f);
#pragma unroll
    for (int i = 0; i < ROWS_PER_CHUNK / 2; ++i) {
        acc = f4add(acc, __ldg(base + (size_t)(2 * i) * HD4));
    }
    sdata[t] = acc;
    __syncthreads();
    if (t < 128) {
        acc = f4add(sdata[t], sdata[t + 128]);
        g_partial4[(b * CHUNKS + chunk) * HD4 + t] = acc;
    }
}

// Stage 2: reduce 64 chunk-partials per (b, column). 4 blocks x 128 threads,
// 64 independent L2 loads per thread (512 KB total, L2-resident).
__global__ void __launch_bounds__(HD4) vsum_kernel() {
    const int b = blockIdx.x;
    const int c = threadIdx.x;
    float4 acc = make_float4(0.f, 0.f, 0.f, 0.f);
#pragma unroll
    for (int k = 0; k < CHUNKS; ++k) {
        acc = f4add(acc, g_partial4[(b * CHUNKS + k) * HD4 + c]);
    }
    g_vsum4[b * HD4 + c] = acc;
}

// Stage 3: broadcast vsum over q. 1024 blocks x 128 threads; each thread
// loads its vsum float4 once then issues 8 STG.128 (one per q row).
#define Q_PER_BLOCK 8
__global__ void __launch_bounds__(HD4) bcast_kernel(float4* __restrict__ out4) {
    const int blk = blockIdx.x;
    const int b = blk >> 8;                      // 256 blocks per batch
    const int q0 = (blk & 255) * Q_PER_BLOCK;
    const int t = threadIdx.x;
    const float4 v = __ldg(&g_vsum4[b * HD4 + t]);
    float4* dst = out4 + ((size_t)(b * L_DIM + q0)) * HD4 + t;
#pragma unroll
    for (int i = 0; i < Q_PER_BLOCK; ++i) {
        dst[(size_t)i * HD4] = v;
    }
}

extern "C" void kernel_launch(void* const* d_in, const int* in_sizes, int n_in,
                              void* d_out, int out_size) {
    // inputs: [0] queries, [1] keys, [2] values (float32). Q, K unused by the math.
    const float4* V4 = (const float4*)d_in[2];
    float4* out4 = (float4*)d_out;

    dim3 g1(CHUNKS, B_DIM);
    vpartial_kernel<<<g1, 256>>>(V4);
    vsum_kernel<<<B_DIM, HD4>>>();
    bcast_kernel<<<B_DIM * (L_DIM / Q_PER_BLOCK), HD4>>>(out4);
}

// round 7
// speedup vs baseline: 1.1687x; 1.1687x over previous
#include <cuda_runtime.h>
#include <cuda_bf16.h>

// Problem: B=4, L=2048, H=8, D=64.
// Reference math collapses: out[b,q,h,d] = (sum_w softmax[.])*(sum_e V[b,e,h,d])
//                                        = 1 * sum_l V[b,l,h,d]
// Q, K are dead inputs. Column-sum V over L, broadcast over q.
// This round: fix stage-1 concurrency (1024 blocks, 8 indep LDG.128/thread),
// parallelize stage-2, fold final 8-way reduce into stage-3.

#define B_DIM 4
#define L_DIM 2048
#define HD4 128            // H*D/4 = 128 float4 per (b,l) row
#define S1_CHUNKS 256      // per batch; 8 rows per chunk
#define S1_ROWS 8
#define S2_GROUPS 8        // per batch; each reduces 32 chunks
#define S2_SPAN 32
#define Q_PER_BLOCK 8

// Scratch (allocation-free __device__ globals)
__device__ float4 g_partial[B_DIM * S1_CHUNKS * HD4];   // 2 MB (L2-resident)
__device__ float4 g_mid[B_DIM * S2_GROUPS * HD4];       // 16 KB

__device__ __forceinline__ float4 f4add(float4 a, float4 b) {
    a.x += b.x; a.y += b.y; a.z += b.z; a.w += b.w; return a;
}

// Stage 1: 1024 blocks x 128 threads. Block = one 8-row chunk of one batch.
// Thread t owns float4-column t; 8 fully independent LDG.128 into 8 regs.
__global__ void __launch_bounds__(HD4) vpartial_kernel(const float4* __restrict__ V4) {
    const int blk = blockIdx.x;
    const int b = blk >> 8;                // 256 chunks per batch
    const int chunk = blk & 255;
    const int t = threadIdx.x;

    const float4* base = V4 + ((size_t)(b * L_DIM + chunk * S1_ROWS)) * HD4 + t;
    float4 r0 = __ldg(base + 0 * HD4);
    float4 r1 = __ldg(base + 1 * HD4);
    float4 r2 = __ldg(base + 2 * HD4);
    float4 r3 = __ldg(base + 3 * HD4);
    float4 r4 = __ldg(base + 4 * HD4);
    float4 r5 = __ldg(base + 5 * HD4);
    float4 r6 = __ldg(base + 6 * HD4);
    float4 r7 = __ldg(base + 7 * HD4);
    float4 s01 = f4add(r0, r1), s23 = f4add(r2, r3);
    float4 s45 = f4add(r4, r5), s67 = f4add(r6, r7);
    g_partial[(b * S1_CHUNKS + chunk) * HD4 + t] =
        f4add(f4add(s01, s23), f4add(s45, s67));
}

// Stage 2: 32 blocks x 128 threads; block (b,g) reduces chunks [g*32, g*32+32)
// from L2-resident g_partial. 4 accumulators for MLP.
__global__ void __launch_bounds__(HD4) vmid_kernel() {
    const int b = blockIdx.x >> 3;
    const int g = blockIdx.x & 7;
    const int t = threadIdx.x;
    const float4* src = g_partial + (b * S1_CHUNKS + g * S2_SPAN) * HD4 + t;
    float4 a0 = make_float4(0.f, 0.f, 0.f, 0.f), a1 = a0, a2 = a0, a3 = a0;
#pragma unroll
    for (int k = 0; k < S2_SPAN; k += 4) {
        a0 = f4add(a0, src[(k + 0) * HD4]);
        a1 = f4add(a1, src[(k + 1) * HD4]);
        a2 = f4add(a2, src[(k + 2) * HD4]);
        a3 = f4add(a3, src[(k + 3) * HD4]);
    }
    g_mid[(b * S2_GROUPS + g) * HD4 + t] = f4add(f4add(a0, a1), f4add(a2, a3));
}

// Stage 3: 1024 blocks x 128 threads. Each thread sums the 8 group-partials
// (16 KB L2-hot table) then broadcasts with 8 STG.128 over q rows.
__global__ void __launch_bounds__(HD4) bcast_kernel(float4* __restrict__ out4) {
    const int blk = blockIdx.x;
    const int b = blk >> 8;                     // 256 blocks per batch
    const int q0 = (blk & 255) * Q_PER_BLOCK;
    const int t = threadIdx.x;

    const float4* m = g_mid + b * S2_GROUPS * HD4 + t;
    float4 v = f4add(f4add(f4add(__ldg(m + 0 * HD4), __ldg(m + 1 * HD4)),
                           f4add(__ldg(m + 2 * HD4), __ldg(m + 3 * HD4))),
                     f4add(f4add(__ldg(m + 4 * HD4), __ldg(m + 5 * HD4)),
                           f4add(__ldg(m + 6 * HD4), __ldg(m + 7 * HD4))));

    float4* dst = out4 + ((size_t)(b * L_DIM + q0)) * HD4 + t;
#pragma unroll
    for (int i = 0; i < Q_PER_BLOCK; ++i)
        dst[(size_t)i * HD4] = v;
}

extern "C" void kernel_launch(void* const* d_in, const int* in_sizes, int n_in,
                              void* d_out, int out_size) {
    // inputs: [0] queries, [1] keys, [2] values (float32). Q, K unused by the math.
    const float4* V4 = (const float4*)d_in[2];
    float4* out4 = (float4*)d_out;

    vpartial_kernel<<<B_DIM * S1_CHUNKS, HD4>>>(V4);
    vmid_kernel<<<B_DIM * S2_GROUPS, HD4>>>();
    bcast_kernel<<<B_DIM * (L_DIM / Q_PER_BLOCK), HD4>>>(out4);
}